// round 13
// baseline (speedup 1.0000x reference)
#include <cuda_runtime.h>
#include <math.h>

// ---------------------------------------------------------------------------
// TFNO4D encoder. Domain after padding: 32^4, channels 32.
// Spectral conv keeps Klist = {0..7, 24..31} in x,y,z; kt = 0..7 in t.
// Per layer: fwd_tz2 -> contract2(y) -> contract2(x) -> mix2 -> contract2(x^-1)
// -> contract2(y^-1) -> fuse_inv (inv-z + inv-t + pointwise + GELU/crop).
// R11 structure; fuse_inv z-chunk 4 (67.7KB smem -> 3 blocks/SM).
// ---------------------------------------------------------------------------

#define NSITE3 32768u
#define NSITE4 1048576u

__device__ float  g_bufA[32u * NSITE4];
__device__ float  g_bufB[32u * NSITE4];
__device__ float2 g_c2[32u * 32u * 32u * 16u * 8u];   // [C][X][Y][kz16][kt8]
__device__ float2 g_c3[32u * 32u * 16u * 16u * 8u];   // y-contracted
__device__ float2 g_c4[32u * 16u * 16u * 16u * 8u];   // [C][kx][ky][kz][kt]
__device__ float2 g_c5[32u * 16u * 16u * 16u * 8u];   // mixed

// Tables
__device__ float2 g_WtT[32 * 8];    // [t][kt]  exp(-2pi i kt t/32)
__device__ float4 g_WfP[32 * 16];   // [z][kzb*2+h] expanded fwd
__device__ float2 g_Wf[16 * 32];    // [a][n] fwd spatial
__device__ float2 g_Wi[32 * 16];    // [n][a] inv spatial
__device__ float  g_ct[32 * 8];     // f_k cos(2pi k t/32), f_0=1 else 2
__device__ float  g_st[32 * 8];     // f_k sin(2pi k t/32)

// Branch-free GELU: erf via Abramowitz-Stegun 7.1.26 (abs err <= 1.5e-7).
__device__ __forceinline__ float gelu_exact(float v) {
    float u = fabsf(v) * 0.70710678118654752f;
    float t = __fdividef(1.0f, fmaf(0.3275911f, u, 1.0f));
    float poly = t * fmaf(t, fmaf(t, fmaf(t, fmaf(t, 1.061405429f, -1.453152027f),
                                          1.421413741f), -0.284496736f), 0.254829592f);
    float e = __expf(-u * u);
    float erf_abs = fmaf(-poly, e, 1.0f);
    float erfv = copysignf(erf_abs, v);
    return 0.5f * v * (1.0f + erfv);
}

__device__ __forceinline__ unsigned long long pk(float a, float b) {
    unsigned long long r;
    asm("mov.b64 %0,{%1,%2};" : "=l"(r) : "f"(a), "f"(b));
    return r;
}
__device__ __forceinline__ float2 upk(unsigned long long u) {
    float2 v;
    asm("mov.b64 {%0,%1},%2;" : "=f"(v.x), "=f"(v.y) : "l"(u));
    return v;
}
__device__ __forceinline__ void fx2(unsigned long long& d, unsigned long long a,
                                    unsigned long long b) {
    asm("fma.rn.f32x2 %0,%1,%2,%0;" : "+l"(d) : "l"(a), "l"(b));
}

// ---------------------------------------------------------------------------
__global__ void init_tables() {
    int tid = threadIdx.x;
    const float STEP = 6.283185307179586f / 32.0f;
    for (int idx = tid; idx < 32 * 8; idx += blockDim.x) {
        int t = idx >> 3, kt = idx & 7;
        float ang = STEP * (float)((kt * t) & 31);
        g_WtT[idx] = make_float2(cosf(ang), -sinf(ang));
        float f = (kt == 0) ? 1.0f : 2.0f;
        g_ct[idx] = f * cosf(ang);
        g_st[idx] = f * sinf(ang);
    }
    for (int idx = tid; idx < 32 * 16; idx += blockDim.x) {
        int z = idx >> 4, r = idx & 15;
        int kzb = r >> 1, h = r & 1;
        int k = h ? (kzb + 24) : kzb;
        float ang = STEP * (float)((k * z) & 31);
        float2 w = make_float2(cosf(ang), -sinf(ang));
        g_WfP[idx] = make_float4(w.x, w.x, -w.y, w.y);
    }
    for (int idx = tid; idx < 16 * 32; idx += blockDim.x) {
        int a = idx >> 5, n = idx & 31;
        int k = (a < 8) ? a : (a + 16);
        float ang = STEP * (float)((k * n) & 31);
        g_Wf[idx] = make_float2(cosf(ang), -sinf(ang));
    }
    for (int idx = tid; idx < 32 * 16; idx += blockDim.x) {
        int n = idx >> 4, a = idx & 15;
        int k = (a < 8) ? a : (a + 16);
        float ang = STEP * (float)((k * n) & 31);
        g_Wi[idx] = make_float2(cosf(ang), sinf(ang));
    }
}

// ---------------------------------------------------------------------------
// Lift: coords + input -> FC(7->16) -> GELU -> FC(16->32), zero outside 24^4.
__global__ void lift_kernel(const float* __restrict__ x,
                            const float* __restrict__ lw1, const float* __restrict__ lb1,
                            const float* __restrict__ lw2, const float* __restrict__ lb2) {
    __shared__ float w1[16 * 7], b1[16], w2[32 * 16], b2[32];
    int tid = threadIdx.x;
    for (int i = tid; i < 112; i += 256) w1[i] = lw1[i];
    for (int i = tid; i < 16; i += 256) b1[i] = lb1[i];
    for (int i = tid; i < 512; i += 256) w2[i] = lw2[i];
    for (int i = tid; i < 32; i += 256) b2[i] = lb2[i];
    __syncthreads();
    unsigned s = blockIdx.x * 256u + (unsigned)tid;
    int t = s & 31, z = (s >> 5) & 31, y = (s >> 10) & 31, xx = s >> 15;
    if (xx < 24 && y < 24 && z < 24 && t < 24) {
        unsigned ii = (((unsigned)xx * 24u + y) * 24u + z) * 24u + t;
        float v[7];
        v[0] = x[ii];
        v[1] = x[331776u + ii];
        v[2] = x[663552u + ii];
        v[3] = xx * (1.0f / 23.0f);
        v[4] = y * (1.0f / 23.0f);
        v[5] = z * (1.0f / 23.0f);
        v[6] = t * (1.0f / 23.0f);
        float h[16];
#pragma unroll
        for (int j = 0; j < 16; j++) {
            float a = b1[j];
#pragma unroll
            for (int c = 0; c < 7; c++) a += w1[j * 7 + c] * v[c];
            h[j] = gelu_exact(a);
        }
#pragma unroll
        for (int o = 0; o < 32; o++) {
            float a = b2[o];
#pragma unroll
            for (int j = 0; j < 16; j++) a += w2[o * 16 + j] * h[j];
            g_bufA[(size_t)o * NSITE4 + s] = a;
        }
    } else {
#pragma unroll
        for (int o = 0; o < 32; o++) g_bufA[(size_t)o * NSITE4 + s] = 0.0f;
    }
}

// ---------------------------------------------------------------------------
// Forward t-DFT (32 real -> 8 complex) + z-DFT (32 -> 16 modes).
// Warp per pencil (c,x,y); 8 pencils per 256-thread block.
__global__ void fwd_tz2(int flip) {
    const float* __restrict__ in = flip ? g_bufB : g_bufA;
    extern __shared__ char smraw[];
    float2* sS = (float2*)smraw;                  // 8 * 544 (row stride 17)
    float2* sCt = sS + 8 * 544;                   // 8 * 256
    float2* sWt = sCt + 2048;                     // 256
    ulonglong2* sWp = (ulonglong2*)(sWt + 256);   // 512
    int tid = threadIdx.x, lane = tid & 31, p = tid >> 5;
    for (int i = tid; i < 256; i += 256) sWt[i] = g_WtT[i];
    {
        const ulonglong2* src = (const ulonglong2*)g_WfP;
        for (int i = tid; i < 512; i += 256) sWp[i] = src[i];
    }
    int c = blockIdx.x >> 7, xx = (blockIdx.x >> 2) & 31, yg = blockIdx.x & 3;
    int y = yg * 8 + p;
    const float4* gp = (const float4*)(in + (size_t)c * NSITE4 + (((size_t)xx * 32u + y) * 32u) * 32u);
#pragma unroll
    for (int q = 0; q < 8; q++) {
        int idx4 = lane + 32 * q;
        float4 v = __ldcs(gp + idx4);
        int idx = idx4 * 2;
        sS[p * 544 + (idx >> 4) * 17 + (idx & 15)] = make_float2(v.x, v.y);
        sS[p * 544 + ((idx + 1) >> 4) * 17 + ((idx + 1) & 15)] = make_float2(v.z, v.w);
    }
    __syncthreads();
    {
        unsigned long long acc[8];
#pragma unroll
        for (int k = 0; k < 8; k++) acc[k] = 0ull;
        const float2* row = sS + p * 544 + lane * 17;
        const ulonglong2* wt2 = (const ulonglong2*)sWt;
#pragma unroll
        for (int tp = 0; tp < 16; tp++) {
            float2 v2 = row[tp];
            unsigned long long v0 = pk(v2.x, v2.x);
            unsigned long long v1 = pk(v2.y, v2.y);
            int t0 = 2 * tp;
#pragma unroll
            for (int kp = 0; kp < 4; kp++) {
                ulonglong2 wa = wt2[t0 * 4 + kp];
                fx2(acc[2 * kp], v0, wa.x);
                fx2(acc[2 * kp + 1], v0, wa.y);
                ulonglong2 wb = wt2[(t0 + 1) * 4 + kp];
                fx2(acc[2 * kp], v1, wb.x);
                fx2(acc[2 * kp + 1], v1, wb.y);
            }
        }
        float2* ct = sCt + p * 256 + lane * 8;
#pragma unroll
        for (int k = 0; k < 8; k++) ct[k] = upk(acc[k]);
    }
    __syncthreads();
    {
        int kzb = lane >> 2, ktq = lane & 3;
        unsigned long long a0 = 0, a1 = 0, a2 = 0, a3 = 0;
        const float2* ctp = sCt + p * 256;
#pragma unroll
        for (int z = 0; z < 32; z++) {
            float2 v0 = ctp[z * 8 + 2 * ktq];
            float2 v1 = ctp[z * 8 + 2 * ktq + 1];
            unsigned long long v0p = pk(v0.x, v0.y), v0s = pk(v0.y, v0.x);
            unsigned long long v1p = pk(v1.x, v1.y), v1s = pk(v1.y, v1.x);
            ulonglong2 wA = sWp[z * 16 + kzb * 2];
            ulonglong2 wB = sWp[z * 16 + kzb * 2 + 1];
            fx2(a0, wA.x, v0p); fx2(a0, wA.y, v0s);
            fx2(a1, wA.x, v1p); fx2(a1, wA.y, v1s);
            fx2(a2, wB.x, v0p); fx2(a2, wB.y, v0s);
            fx2(a3, wB.x, v1p); fx2(a3, wB.y, v1s);
        }
        float2* ob = g_c2 + (((size_t)c * 32u + xx) * 32u + y) * 128u;
        float2 r0 = upk(a0), r1 = upk(a1), r2 = upk(a2), r3 = upk(a3);
        *(float4*)(ob + kzb * 8 + 2 * ktq) = make_float4(r0.x, r0.y, r1.x, r1.y);
        *(float4*)(ob + (kzb + 8) * 8 + 2 * ktq) = make_float4(r2.x, r2.y, r3.x, r3.y);
    }
}

// ---------------------------------------------------------------------------
// Tiled complex contraction: out[k,i] = sum_n W[k,n] in[n,i].
template <int M, int L, bool FWD>
__global__ void contract2(const float2* __restrict__ in, float2* __restrict__ out,
                          int inner, int tiles) {
    constexpr int ITILE = 2048 / M;
    constexpr int IG = ITILE / 2;
    __shared__ float2 sW[M * L];
    __shared__ float2 sIn[L * ITILE];
    int outer = blockIdx.x / tiles;
    int tile = blockIdx.x - outer * tiles;
    int base = tile * ITILE;
    int tid = threadIdx.x;
    const float2* Wt = FWD ? g_Wf : g_Wi;
    for (int i = tid; i < M * L; i += 256) sW[i] = Wt[i];
    {
        const float4* ip4 = reinterpret_cast<const float4*>(in + (size_t)outer * L * inner + base);
        float4* s4 = reinterpret_cast<float4*>(sIn);
        constexpr int R4 = ITILE / 2;
        for (int idx = tid; idx < L * R4; idx += 256) {
            int n = idx / R4, r = idx - n * R4;
            s4[n * R4 + r] = ip4[(size_t)n * (inner >> 1) + r];
        }
    }
    __syncthreads();
    int ig = tid & (IG - 1);
    int kg = tid / IG;
    float2 acc[4][2];
#pragma unroll
    for (int kk = 0; kk < 4; kk++) {
        acc[kk][0] = make_float2(0.f, 0.f);
        acc[kk][1] = make_float2(0.f, 0.f);
    }
    const float4* s4 = reinterpret_cast<const float4*>(sIn);
#pragma unroll
    for (int n = 0; n < L; n++) {
        float4 v = s4[n * (ITILE / 2) + ig];
#pragma unroll
        for (int kk = 0; kk < 4; kk++) {
            float2 w = sW[(kg * 4 + kk) * L + n];
            acc[kk][0].x += w.x * v.x - w.y * v.y;
            acc[kk][0].y += w.x * v.y + w.y * v.x;
            acc[kk][1].x += w.x * v.z - w.y * v.w;
            acc[kk][1].y += w.x * v.w + w.y * v.z;
        }
    }
#pragma unroll
    for (int kk = 0; kk < 4; kk++) {
        int k = kg * 4 + kk;
        float4* op4 = reinterpret_cast<float4*>(out + ((size_t)outer * M + k) * inner + base);
        op4[ig] = make_float4(acc[kk][0].x, acc[kk][0].y, acc[kk][1].x, acc[kk][1].y);
    }
}

// ---------------------------------------------------------------------------
// Mode mixing: per corner (8) and (m1,m2), 64 contiguous (m3,m4) modes.
__global__ void mix2(const float* __restrict__ wbase) {
    __shared__ float2 sIn[32 * 64];
    int bidx = blockIdx.x;
    int m2 = bidx & 7, m1 = (bidx >> 3) & 7, corner = bidx >> 6;
    int cz = corner & 1, cy = (corner >> 1) & 1, cx = corner >> 2;
    int kx = cx * 8 + m1, ky = cy * 8 + m2;
    int tid = threadIdx.x;  // 256
    unsigned base = (((unsigned)kx * 16u + ky) * 16u + (unsigned)cz * 8u) * 8u;
    {
        const float4* src4 = (const float4*)g_c4;
        float4* sIn4 = (float4*)sIn;
#pragma unroll
        for (int q = 0; q < 4; q++) {
            int idx = tid + 256 * q;
            int cc = idx >> 5, f = idx & 31;
            sIn4[cc * 32 + f] = src4[(size_t)cc * 16384u + (base >> 1) + f];
        }
    }
    __syncthreads();
    int og = tid >> 5, mp = tid & 31;
    float acc[4][4];
#pragma unroll
    for (int o = 0; o < 4; o++)
#pragma unroll
        for (int j = 0; j < 4; j++) acc[o][j] = 0.f;
    const float* wp0 = wbase + (size_t)corner * 8388608u + (size_t)(og * 4) * 8192u +
                       (size_t)(m1 * 8 + m2) * 128u + mp * 4;
    const float4* sIn4 = (const float4*)sIn;
#pragma unroll 4
    for (int c = 0; c < 32; c++) {
        float4 v = sIn4[c * 32 + mp];
        const float* wc = wp0 + (size_t)c * 262144u;
#pragma unroll
        for (int o = 0; o < 4; o++) {
            float4 w = __ldcs((const float4*)(wc + (size_t)o * 8192u));
            acc[o][0] += w.x * v.x - w.y * v.y;
            acc[o][1] += w.x * v.y + w.y * v.x;
            acc[o][2] += w.z * v.z - w.w * v.w;
            acc[o][3] += w.z * v.w + w.w * v.z;
        }
    }
    const float scale = 1.0f / 1048576.0f;
    float4* dst = (float4*)g_c5;
#pragma unroll
    for (int o = 0; o < 4; o++) {
        dst[(size_t)(og * 4 + o) * 16384u + (base >> 1) + mp] =
            make_float4(acc[o][0] * scale, acc[o][1] * scale,
                        acc[o][2] * scale, acc[o][3] * scale);
    }
}

// ---------------------------------------------------------------------------
// Fused inverse-z DFT + inverse-t real DFT + pointwise conv + bias
// (+GELU or crop). One block per (x,y), 512 threads, z-chunk 4 (67.7KB smem,
// 3 blocks/SM). Thread = (tp16, zq4, og8): owns 4 o x 1 z x 2 t.
__global__ void __launch_bounds__(512, 3)
fuse_inv_kernel(int flip, const float* __restrict__ cw,
                const float* __restrict__ cb,
                float* __restrict__ outcrop, int apply_gelu) {
    extern __shared__ char smemraw[];
    float2* sC = reinterpret_cast<float2*>(smemraw);            // 4096 [o][kz][kt]  32KB
    float2* sA = sC + 4096;                                     // 1024 [o][z4][kt]   8KB
    float2* sWi = sA + 1024;                                    // 512                4KB
    float*  sX = reinterpret_cast<float*>(sWi + 512);           // 4096 [c][z4][t]   16KB
    float*  sW = sX + 4096;                                     // 1024 [c][o]        4KB
    float*  sB = sW + 1024;                                     // 32
    unsigned long long* sCt2 = reinterpret_cast<unsigned long long*>(sB + 32);  // 128 [tp][kt]
    unsigned long long* sSt2 = sCt2 + 128;                      // 128 (negated sin)

    int bx = blockIdx.x;
    int xx = bx >> 5, y = bx & 31;
    if (outcrop && (xx >= 24 || y >= 24)) return;
    const float* __restrict__ xin = flip ? g_bufB : g_bufA;
    float* __restrict__ outfull = flip ? g_bufA : g_bufB;
    int tid = threadIdx.x;  // 512

    {
        const float4* src = reinterpret_cast<const float4*>(g_c2);
        float4* dst = reinterpret_cast<float4*>(sC);
#pragma unroll
        for (int q = 0; q < 4; q++) {
            int idx4 = tid + 512 * q;
            int o = idx4 >> 6, r = idx4 & 63;
            dst[idx4] = src[(((size_t)o * 32u + xx) * 32u + y) * 64u + r];
        }
    }
    sWi[tid] = g_Wi[tid];
    // transpose conv weights into [c][o]
    sW[tid] = cw[(tid & 31) * 32 + (tid >> 5)];
    {
        int i1 = tid + 512;
        sW[i1] = cw[(i1 & 31) * 32 + (i1 >> 5)];
    }
    if (tid < 32) sB[tid] = cb[tid];
    if (tid < 128) {
        int tpp = tid >> 3, kt = tid & 7;
        sCt2[tid] = pk(g_ct[(2 * tpp) * 8 + kt], g_ct[(2 * tpp + 1) * 8 + kt]);
        sSt2[tid] = pk(-g_st[(2 * tpp) * 8 + kt], -g_st[(2 * tpp + 1) * 8 + kt]);
    }

    int tp = tid & 15, zq = (tid >> 4) & 3, og = tid >> 6;  // og 0..7
    int ob = og * 4;

    for (int zb = 0; zb < 32; zb += 4) {
        if (outcrop && zb >= 24) break;
        // prefetch x chunk into registers: [c32][z4][t32] = 4096 floats
        float4 xr[2];
#pragma unroll
        for (int q = 0; q < 2; q++) {
            int idx4 = tid + 512 * q;
            int c = idx4 >> 5, r = idx4 & 31;
            xr[q] = __ldcs(reinterpret_cast<const float4*>(
                xin + (size_t)c * NSITE4 + (((size_t)xx * 32u + y) * 32u + zb) * 32u) + r);
        }
        __syncthreads();
        // inverse-z: a[o][z][kt] = sum_kz Wi[zb+z][kz] * sC[o][kz][kt]
        // 1024 items = [32o][4z][8kt]; 512 threads x 2.
#pragma unroll
        for (int j = 0; j < 2; j++) {
            int idx = tid + 512 * j;
            int o = idx >> 5, rem = idx & 31;
            int z = rem >> 3, kt = rem & 7;
            float2 a = make_float2(0.f, 0.f);
#pragma unroll
            for (int kz = 0; kz < 16; kz++) {
                float2 w = sWi[(zb + z) * 16 + kz];
                float2 v = sC[(o * 16 + kz) * 8 + kt];
                a.x += w.x * v.x - w.y * v.y;
                a.y += w.x * v.y + w.y * v.x;
            }
            sA[(o * 4 + z) * 8 + kt] = a;
        }
        {
            float4* dst = reinterpret_cast<float4*>(sX);
#pragma unroll
            for (int q = 0; q < 2; q++) dst[tid + 512 * q] = xr[q];
        }
        __syncthreads();
        // pointwise conv, t-pair packed: acc[o] holds (t0, t0+1) at z = zq
        unsigned long long acc[4];
#pragma unroll
        for (int o = 0; o < 4; o++) {
            float b = sB[ob + o];
            acc[o] = pk(b, b);
        }
#pragma unroll
        for (int c = 0; c < 32; c++) {
            float4 w4 = *reinterpret_cast<const float4*>(&sW[c * 32 + ob]);
            unsigned long long x0 = *reinterpret_cast<const unsigned long long*>(
                &sX[c * 128 + zq * 32 + 2 * tp]);
            fx2(acc[0], pk(w4.x, w4.x), x0);
            fx2(acc[1], pk(w4.y, w4.y), x0);
            fx2(acc[2], pk(w4.z, w4.z), x0);
            fx2(acc[3], pk(w4.w, w4.w), x0);
        }
        // inverse-t: acc += a.x * ct2 + a.y * (-st2)
#pragma unroll
        for (int kt = 0; kt < 8; kt++) {
            unsigned long long c2v = sCt2[tp * 8 + kt];
            unsigned long long s2v = sSt2[tp * 8 + kt];
#pragma unroll
            for (int o = 0; o < 4; o++) {
                float2 a = sA[((ob + o) * 4 + zq) * 8 + kt];
                fx2(acc[o], pk(a.x, a.x), c2v);
                fx2(acc[o], pk(a.y, a.y), s2v);
            }
        }
        int z = zb + zq;
        if (outcrop) {
            if (tp < 12) {  // t = 2tp, 2tp+1 < 24
#pragma unroll
                for (int o = 0; o < 4; o++) {
                    float2 v = upk(acc[o]);
                    unsigned oidx = (((unsigned)xx * 24u + y) * 24u + z) * 24u + 2 * tp;
                    __stcs(reinterpret_cast<float2*>(
                               outcrop + (size_t)(ob + o) * 331776u + oidx), v);
                }
            }
        } else {
#pragma unroll
            for (int o = 0; o < 4; o++) {
                float2 v = upk(acc[o]);
                if (apply_gelu) { v.x = gelu_exact(v.x); v.y = gelu_exact(v.y); }
                size_t base = (size_t)(ob + o) * NSITE4 +
                              (((size_t)xx * 32u + y) * 32u + z) * 32u + 2 * tp;
                __stcs(reinterpret_cast<float2*>(outfull + base), v);
            }
        }
    }
}

// ---------------------------------------------------------------------------
extern "C" void kernel_launch(void* const* d_in, const int* in_sizes, int n_in,
                              void* d_out, int out_size) {
    const float* x = (const float*)d_in[0];
    const float* lw1 = (const float*)d_in[1];
    const float* lb1 = (const float*)d_in[2];
    const float* lw2 = (const float*)d_in[3];
    const float* lb2 = (const float*)d_in[4];
    const float* cw = (const float*)d_in[5];
    const float* cb = (const float*)d_in[6];
    const float* sw = (const float*)d_in[7];

    void *c2p, *c3p, *c4p, *c5p;
    cudaGetSymbolAddress(&c2p, g_c2);
    cudaGetSymbolAddress(&c3p, g_c3);
    cudaGetSymbolAddress(&c4p, g_c4);
    cudaGetSymbolAddress(&c5p, g_c5);
    float2* c2 = (float2*)c2p;
    float2* c3 = (float2*)c3p;
    float2* c4 = (float2*)c4p;
    float2* c5 = (float2*)c5p;

    const int SM_TZ = 61440;
    // 32768 + 8192 + 4096 + 16384 + 4096 + 128 + 2048 = 67712
    const int SM_FUSE = 67712;
    cudaFuncSetAttribute(fwd_tz2, cudaFuncAttributeMaxDynamicSharedMemorySize, SM_TZ);
    cudaFuncSetAttribute(fuse_inv_kernel, cudaFuncAttributeMaxDynamicSharedMemorySize, SM_FUSE);

    init_tables<<<1, 256>>>();
    lift_kernel<<<4096, 256>>>(x, lw1, lb1, lw2, lb2);

    for (int k = 0; k < 4; k++) {
        int flip = k & 1;
        fwd_tz2<<<4096, 256, SM_TZ>>>(flip);
        contract2<16, 32, true><<<1024, 256>>>(c2, c3, 128, 1);    // y: 32 -> 16
        contract2<16, 32, true><<<512, 256>>>(c3, c4, 2048, 16);   // x: 32 -> 16
        mix2<<<512, 256>>>(sw + (size_t)k * 67108864u);
        contract2<32, 16, false><<<1024, 256>>>(c5, c3, 2048, 32); // x: 16 -> 32
        contract2<32, 16, false><<<2048, 256>>>(c3, c2, 128, 2);   // y: 16 -> 32
        fuse_inv_kernel<<<1024, 512, SM_FUSE>>>(flip, cw + k * 1024, cb + k * 32,
                                                (k == 3) ? (float*)d_out : nullptr,
                                                (k < 3) ? 1 : 0);
    }
}

// round 14
// speedup vs baseline: 1.6040x; 1.6040x over previous
#include <cuda_runtime.h>
#include <math.h>

// ---------------------------------------------------------------------------
// TFNO4D encoder. Domain after padding: 32^4, channels 32.
// Spectral conv keeps Klist = {0..7, 24..31} in x,y,z; kt = 0..7 in t.
// Per layer: fwd_tz2 -> contract2(y) -> contract2(x) -> mix2 -> contract2(x^-1)
// -> contract2(y^-1) -> fuse_inv (inv-z + inv-t + pointwise + GELU/crop).
// R11 structure (best, 1394us); contract2 n-pair LDS.128 weight loads.
// ---------------------------------------------------------------------------

#define NSITE3 32768u
#define NSITE4 1048576u

__device__ float  g_bufA[32u * NSITE4];
__device__ float  g_bufB[32u * NSITE4];
__device__ float2 g_c2[32u * 32u * 32u * 16u * 8u];   // [C][X][Y][kz16][kt8]
__device__ float2 g_c3[32u * 32u * 16u * 16u * 8u];   // y-contracted
__device__ float2 g_c4[32u * 16u * 16u * 16u * 8u];   // [C][kx][ky][kz][kt]
__device__ float2 g_c5[32u * 16u * 16u * 16u * 8u];   // mixed

// Tables
__device__ float2 g_WtT[32 * 8];    // [t][kt]  exp(-2pi i kt t/32)
__device__ float4 g_WfP[32 * 16];   // [z][kzb*2+h] expanded fwd
__device__ float2 g_Wf[16 * 32];    // [a][n] fwd spatial
__device__ float2 g_Wi[32 * 16];    // [n][a] inv spatial
__device__ float  g_ct[32 * 8];     // f_k cos(2pi k t/32), f_0=1 else 2
__device__ float  g_st[32 * 8];     // f_k sin(2pi k t/32)

// Branch-free GELU: erf via Abramowitz-Stegun 7.1.26 (abs err <= 1.5e-7).
__device__ __forceinline__ float gelu_exact(float v) {
    float u = fabsf(v) * 0.70710678118654752f;
    float t = __fdividef(1.0f, fmaf(0.3275911f, u, 1.0f));
    float poly = t * fmaf(t, fmaf(t, fmaf(t, fmaf(t, 1.061405429f, -1.453152027f),
                                          1.421413741f), -0.284496736f), 0.254829592f);
    float e = __expf(-u * u);
    float erf_abs = fmaf(-poly, e, 1.0f);
    float erfv = copysignf(erf_abs, v);
    return 0.5f * v * (1.0f + erfv);
}

__device__ __forceinline__ unsigned long long pk(float a, float b) {
    unsigned long long r;
    asm("mov.b64 %0,{%1,%2};" : "=l"(r) : "f"(a), "f"(b));
    return r;
}
__device__ __forceinline__ float2 upk(unsigned long long u) {
    float2 v;
    asm("mov.b64 {%0,%1},%2;" : "=f"(v.x), "=f"(v.y) : "l"(u));
    return v;
}
__device__ __forceinline__ void fx2(unsigned long long& d, unsigned long long a,
                                    unsigned long long b) {
    asm("fma.rn.f32x2 %0,%1,%2,%0;" : "+l"(d) : "l"(a), "l"(b));
}

// ---------------------------------------------------------------------------
__global__ void init_tables() {
    int tid = threadIdx.x;
    const float STEP = 6.283185307179586f / 32.0f;
    for (int idx = tid; idx < 32 * 8; idx += blockDim.x) {
        int t = idx >> 3, kt = idx & 7;
        float ang = STEP * (float)((kt * t) & 31);
        g_WtT[idx] = make_float2(cosf(ang), -sinf(ang));
        float f = (kt == 0) ? 1.0f : 2.0f;
        g_ct[idx] = f * cosf(ang);
        g_st[idx] = f * sinf(ang);
    }
    for (int idx = tid; idx < 32 * 16; idx += blockDim.x) {
        int z = idx >> 4, r = idx & 15;
        int kzb = r >> 1, h = r & 1;
        int k = h ? (kzb + 24) : kzb;
        float ang = STEP * (float)((k * z) & 31);
        float2 w = make_float2(cosf(ang), -sinf(ang));
        g_WfP[idx] = make_float4(w.x, w.x, -w.y, w.y);
    }
    for (int idx = tid; idx < 16 * 32; idx += blockDim.x) {
        int a = idx >> 5, n = idx & 31;
        int k = (a < 8) ? a : (a + 16);
        float ang = STEP * (float)((k * n) & 31);
        g_Wf[idx] = make_float2(cosf(ang), -sinf(ang));
    }
    for (int idx = tid; idx < 32 * 16; idx += blockDim.x) {
        int n = idx >> 4, a = idx & 15;
        int k = (a < 8) ? a : (a + 16);
        float ang = STEP * (float)((k * n) & 31);
        g_Wi[idx] = make_float2(cosf(ang), sinf(ang));
    }
}

// ---------------------------------------------------------------------------
// Lift: coords + input -> FC(7->16) -> GELU -> FC(16->32), zero outside 24^4.
__global__ void lift_kernel(const float* __restrict__ x,
                            const float* __restrict__ lw1, const float* __restrict__ lb1,
                            const float* __restrict__ lw2, const float* __restrict__ lb2) {
    __shared__ float w1[16 * 7], b1[16], w2[32 * 16], b2[32];
    int tid = threadIdx.x;
    for (int i = tid; i < 112; i += 256) w1[i] = lw1[i];
    for (int i = tid; i < 16; i += 256) b1[i] = lb1[i];
    for (int i = tid; i < 512; i += 256) w2[i] = lw2[i];
    for (int i = tid; i < 32; i += 256) b2[i] = lb2[i];
    __syncthreads();
    unsigned s = blockIdx.x * 256u + (unsigned)tid;
    int t = s & 31, z = (s >> 5) & 31, y = (s >> 10) & 31, xx = s >> 15;
    if (xx < 24 && y < 24 && z < 24 && t < 24) {
        unsigned ii = (((unsigned)xx * 24u + y) * 24u + z) * 24u + t;
        float v[7];
        v[0] = x[ii];
        v[1] = x[331776u + ii];
        v[2] = x[663552u + ii];
        v[3] = xx * (1.0f / 23.0f);
        v[4] = y * (1.0f / 23.0f);
        v[5] = z * (1.0f / 23.0f);
        v[6] = t * (1.0f / 23.0f);
        float h[16];
#pragma unroll
        for (int j = 0; j < 16; j++) {
            float a = b1[j];
#pragma unroll
            for (int c = 0; c < 7; c++) a += w1[j * 7 + c] * v[c];
            h[j] = gelu_exact(a);
        }
#pragma unroll
        for (int o = 0; o < 32; o++) {
            float a = b2[o];
#pragma unroll
            for (int j = 0; j < 16; j++) a += w2[o * 16 + j] * h[j];
            g_bufA[(size_t)o * NSITE4 + s] = a;
        }
    } else {
#pragma unroll
        for (int o = 0; o < 32; o++) g_bufA[(size_t)o * NSITE4 + s] = 0.0f;
    }
}

// ---------------------------------------------------------------------------
// Forward t-DFT (32 real -> 8 complex) + z-DFT (32 -> 16 modes).
// Warp per pencil (c,x,y); 8 pencils per 256-thread block.
__global__ void fwd_tz2(int flip) {
    const float* __restrict__ in = flip ? g_bufB : g_bufA;
    extern __shared__ char smraw[];
    float2* sS = (float2*)smraw;                  // 8 * 544 (row stride 17)
    float2* sCt = sS + 8 * 544;                   // 8 * 256
    float2* sWt = sCt + 2048;                     // 256
    ulonglong2* sWp = (ulonglong2*)(sWt + 256);   // 512
    int tid = threadIdx.x, lane = tid & 31, p = tid >> 5;
    for (int i = tid; i < 256; i += 256) sWt[i] = g_WtT[i];
    {
        const ulonglong2* src = (const ulonglong2*)g_WfP;
        for (int i = tid; i < 512; i += 256) sWp[i] = src[i];
    }
    int c = blockIdx.x >> 7, xx = (blockIdx.x >> 2) & 31, yg = blockIdx.x & 3;
    int y = yg * 8 + p;
    const float4* gp = (const float4*)(in + (size_t)c * NSITE4 + (((size_t)xx * 32u + y) * 32u) * 32u);
#pragma unroll
    for (int q = 0; q < 8; q++) {
        int idx4 = lane + 32 * q;
        float4 v = __ldcs(gp + idx4);
        int idx = idx4 * 2;
        sS[p * 544 + (idx >> 4) * 17 + (idx & 15)] = make_float2(v.x, v.y);
        sS[p * 544 + ((idx + 1) >> 4) * 17 + ((idx + 1) & 15)] = make_float2(v.z, v.w);
    }
    __syncthreads();
    {
        unsigned long long acc[8];
#pragma unroll
        for (int k = 0; k < 8; k++) acc[k] = 0ull;
        const float2* row = sS + p * 544 + lane * 17;
        const ulonglong2* wt2 = (const ulonglong2*)sWt;
#pragma unroll
        for (int tp = 0; tp < 16; tp++) {
            float2 v2 = row[tp];
            unsigned long long v0 = pk(v2.x, v2.x);
            unsigned long long v1 = pk(v2.y, v2.y);
            int t0 = 2 * tp;
#pragma unroll
            for (int kp = 0; kp < 4; kp++) {
                ulonglong2 wa = wt2[t0 * 4 + kp];
                fx2(acc[2 * kp], v0, wa.x);
                fx2(acc[2 * kp + 1], v0, wa.y);
                ulonglong2 wb = wt2[(t0 + 1) * 4 + kp];
                fx2(acc[2 * kp], v1, wb.x);
                fx2(acc[2 * kp + 1], v1, wb.y);
            }
        }
        float2* ct = sCt + p * 256 + lane * 8;
#pragma unroll
        for (int k = 0; k < 8; k++) ct[k] = upk(acc[k]);
    }
    __syncthreads();
    {
        int kzb = lane >> 2, ktq = lane & 3;
        unsigned long long a0 = 0, a1 = 0, a2 = 0, a3 = 0;
        const float2* ctp = sCt + p * 256;
#pragma unroll
        for (int z = 0; z < 32; z++) {
            float2 v0 = ctp[z * 8 + 2 * ktq];
            float2 v1 = ctp[z * 8 + 2 * ktq + 1];
            unsigned long long v0p = pk(v0.x, v0.y), v0s = pk(v0.y, v0.x);
            unsigned long long v1p = pk(v1.x, v1.y), v1s = pk(v1.y, v1.x);
            ulonglong2 wA = sWp[z * 16 + kzb * 2];
            ulonglong2 wB = sWp[z * 16 + kzb * 2 + 1];
            fx2(a0, wA.x, v0p); fx2(a0, wA.y, v0s);
            fx2(a1, wA.x, v1p); fx2(a1, wA.y, v1s);
            fx2(a2, wB.x, v0p); fx2(a2, wB.y, v0s);
            fx2(a3, wB.x, v1p); fx2(a3, wB.y, v1s);
        }
        float2* ob = g_c2 + (((size_t)c * 32u + xx) * 32u + y) * 128u;
        float2 r0 = upk(a0), r1 = upk(a1), r2 = upk(a2), r3 = upk(a3);
        *(float4*)(ob + kzb * 8 + 2 * ktq) = make_float4(r0.x, r0.y, r1.x, r1.y);
        *(float4*)(ob + (kzb + 8) * 8 + 2 * ktq) = make_float4(r2.x, r2.y, r3.x, r3.y);
    }
}

// ---------------------------------------------------------------------------
// Tiled complex contraction: out[k,i] = sum_n W[k,n] in[n,i].
// n-pair stepping: adjacent-n weights fetched as one LDS.128.
template <int M, int L, bool FWD>
__global__ void contract2(const float2* __restrict__ in, float2* __restrict__ out,
                          int inner, int tiles) {
    constexpr int ITILE = 2048 / M;
    constexpr int IG = ITILE / 2;
    __shared__ __align__(16) float2 sW[M * L];
    __shared__ float2 sIn[L * ITILE];
    int outer = blockIdx.x / tiles;
    int tile = blockIdx.x - outer * tiles;
    int base = tile * ITILE;
    int tid = threadIdx.x;
    const float2* Wt = FWD ? g_Wf : g_Wi;
    for (int i = tid; i < M * L; i += 256) sW[i] = Wt[i];
    {
        const float4* ip4 = reinterpret_cast<const float4*>(in + (size_t)outer * L * inner + base);
        float4* s4 = reinterpret_cast<float4*>(sIn);
        constexpr int R4 = ITILE / 2;
        for (int idx = tid; idx < L * R4; idx += 256) {
            int n = idx / R4, r = idx - n * R4;
            s4[n * R4 + r] = ip4[(size_t)n * (inner >> 1) + r];
        }
    }
    __syncthreads();
    int ig = tid & (IG - 1);
    int kg = tid / IG;
    float2 acc[4][2];
#pragma unroll
    for (int kk = 0; kk < 4; kk++) {
        acc[kk][0] = make_float2(0.f, 0.f);
        acc[kk][1] = make_float2(0.f, 0.f);
    }
    const float4* s4 = reinterpret_cast<const float4*>(sIn);
#pragma unroll
    for (int n = 0; n < L; n += 2) {
        float4 va = s4[n * (ITILE / 2) + ig];
        float4 vb = s4[(n + 1) * (ITILE / 2) + ig];
#pragma unroll
        for (int kk = 0; kk < 4; kk++) {
            float4 w2 = *reinterpret_cast<const float4*>(&sW[(kg * 4 + kk) * L + n]);
            // n even: w = (w2.x, w2.y)
            acc[kk][0].x += w2.x * va.x - w2.y * va.y;
            acc[kk][0].y += w2.x * va.y + w2.y * va.x;
            acc[kk][1].x += w2.x * va.z - w2.y * va.w;
            acc[kk][1].y += w2.x * va.w + w2.y * va.z;
            // n odd: w = (w2.z, w2.w)
            acc[kk][0].x += w2.z * vb.x - w2.w * vb.y;
            acc[kk][0].y += w2.z * vb.y + w2.w * vb.x;
            acc[kk][1].x += w2.z * vb.z - w2.w * vb.w;
            acc[kk][1].y += w2.z * vb.w + w2.w * vb.z;
        }
    }
#pragma unroll
    for (int kk = 0; kk < 4; kk++) {
        int k = kg * 4 + kk;
        float4* op4 = reinterpret_cast<float4*>(out + ((size_t)outer * M + k) * inner + base);
        op4[ig] = make_float4(acc[kk][0].x, acc[kk][0].y, acc[kk][1].x, acc[kk][1].y);
    }
}

// ---------------------------------------------------------------------------
// Mode mixing: per corner (8) and (m1,m2), 64 contiguous (m3,m4) modes.
__global__ void mix2(const float* __restrict__ wbase) {
    __shared__ float2 sIn[32 * 64];
    int bidx = blockIdx.x;
    int m2 = bidx & 7, m1 = (bidx >> 3) & 7, corner = bidx >> 6;
    int cz = corner & 1, cy = (corner >> 1) & 1, cx = corner >> 2;
    int kx = cx * 8 + m1, ky = cy * 8 + m2;
    int tid = threadIdx.x;  // 256
    unsigned base = (((unsigned)kx * 16u + ky) * 16u + (unsigned)cz * 8u) * 8u;
    {
        const float4* src4 = (const float4*)g_c4;
        float4* sIn4 = (float4*)sIn;
#pragma unroll
        for (int q = 0; q < 4; q++) {
            int idx = tid + 256 * q;
            int cc = idx >> 5, f = idx & 31;
            sIn4[cc * 32 + f] = src4[(size_t)cc * 16384u + (base >> 1) + f];
        }
    }
    __syncthreads();
    int og = tid >> 5, mp = tid & 31;
    float acc[4][4];
#pragma unroll
    for (int o = 0; o < 4; o++)
#pragma unroll
        for (int j = 0; j < 4; j++) acc[o][j] = 0.f;
    const float* wp0 = wbase + (size_t)corner * 8388608u + (size_t)(og * 4) * 8192u +
                       (size_t)(m1 * 8 + m2) * 128u + mp * 4;
    const float4* sIn4 = (const float4*)sIn;
#pragma unroll 4
    for (int c = 0; c < 32; c++) {
        float4 v = sIn4[c * 32 + mp];
        const float* wc = wp0 + (size_t)c * 262144u;
#pragma unroll
        for (int o = 0; o < 4; o++) {
            float4 w = __ldcs((const float4*)(wc + (size_t)o * 8192u));
            acc[o][0] += w.x * v.x - w.y * v.y;
            acc[o][1] += w.x * v.y + w.y * v.x;
            acc[o][2] += w.z * v.z - w.w * v.w;
            acc[o][3] += w.z * v.w + w.w * v.z;
        }
    }
    const float scale = 1.0f / 1048576.0f;
    float4* dst = (float4*)g_c5;
#pragma unroll
    for (int o = 0; o < 4; o++) {
        dst[(size_t)(og * 4 + o) * 16384u + (base >> 1) + mp] =
            make_float4(acc[o][0] * scale, acc[o][1] * scale,
                        acc[o][2] * scale, acc[o][3] * scale);
    }
}

// ---------------------------------------------------------------------------
// Fused inverse-z DFT + inverse-t real DFT + pointwise conv + bias
// (+GELU or crop). One block per (x,y), 512 threads.
// Thread = (tp16, zq4, og8): owns 4 o x 2 z x 2 t (t-pair packed FFMA2).
__global__ void fuse_inv_kernel(int flip, const float* __restrict__ cw,
                                const float* __restrict__ cb,
                                float* __restrict__ outcrop, int apply_gelu) {
    extern __shared__ char smemraw[];
    float2* sC = reinterpret_cast<float2*>(smemraw);            // 4096 [o][kz][kt]
    float2* sA = sC + 4096;                                     // 2048 [o][z8][kt]
    float2* sWi = sA + 2048;                                    // 512
    float*  sX = reinterpret_cast<float*>(sWi + 512);           // 8192 [c][z8][t]
    float*  sW = sX + 8192;                                     // 1024 [c][o] transposed
    float*  sB = sW + 1024;                                     // 32
    unsigned long long* sCt2 = reinterpret_cast<unsigned long long*>(sB + 32);  // 128 [tp][kt]
    unsigned long long* sSt2 = sCt2 + 128;                      // 128 (negated sin)

    int bx = blockIdx.x;
    int xx = bx >> 5, y = bx & 31;
    if (outcrop && (xx >= 24 || y >= 24)) return;
    const float* __restrict__ xin = flip ? g_bufB : g_bufA;
    float* __restrict__ outfull = flip ? g_bufA : g_bufB;
    int tid = threadIdx.x;  // 512

    {
        const float4* src = reinterpret_cast<const float4*>(g_c2);
        float4* dst = reinterpret_cast<float4*>(sC);
#pragma unroll
        for (int q = 0; q < 4; q++) {
            int idx4 = tid + 512 * q;
            int o = idx4 >> 6, r = idx4 & 63;
            dst[idx4] = src[(((size_t)o * 32u + xx) * 32u + y) * 64u + r];
        }
    }
    sWi[tid] = g_Wi[tid];
    // transpose conv weights into [c][o]
    sW[tid] = cw[(tid & 31) * 32 + (tid >> 5)];
    {
        int i1 = tid + 512;
        sW[i1] = cw[(i1 & 31) * 32 + (i1 >> 5)];
    }
    if (tid < 32) sB[tid] = cb[tid];
    if (tid < 128) {
        int tpp = tid >> 3, kt = tid & 7;
        sCt2[tid] = pk(g_ct[(2 * tpp) * 8 + kt], g_ct[(2 * tpp + 1) * 8 + kt]);
        sSt2[tid] = pk(-g_st[(2 * tpp) * 8 + kt], -g_st[(2 * tpp + 1) * 8 + kt]);
    }

    int tp = tid & 15, zq = (tid >> 4) & 3, og = tid >> 6;  // og 0..7
    int ob = og * 4, z0 = zq * 2;

    for (int zb = 0; zb < 32; zb += 8) {
        if (outcrop && zb >= 24) break;
        // prefetch x chunk into registers
        float4 xr[4];
#pragma unroll
        for (int q = 0; q < 4; q++) {
            int idx4 = tid + 512 * q;
            int c = idx4 >> 6, r = idx4 & 63;
            xr[q] = __ldcs(reinterpret_cast<const float4*>(
                xin + (size_t)c * NSITE4 + (((size_t)xx * 32u + y) * 32u + zb) * 32u) + r);
        }
        __syncthreads();
        // inverse-z: a[o][z][kt] = sum_kz Wi[zb+z][kz] * sC[o][kz][kt]
#pragma unroll
        for (int j = 0; j < 4; j++) {
            int idx = tid + 512 * j;
            int o = idx >> 6, rem = idx & 63;
            int z = rem >> 3, kt = rem & 7;
            float2 a = make_float2(0.f, 0.f);
#pragma unroll
            for (int kz = 0; kz < 16; kz++) {
                float2 w = sWi[(zb + z) * 16 + kz];
                float2 v = sC[(o * 16 + kz) * 8 + kt];
                a.x += w.x * v.x - w.y * v.y;
                a.y += w.x * v.y + w.y * v.x;
            }
            sA[(o * 8 + z) * 8 + kt] = a;
        }
        {
            float4* dst = reinterpret_cast<float4*>(sX);
#pragma unroll
            for (int q = 0; q < 4; q++) dst[tid + 512 * q] = xr[q];
        }
        __syncthreads();
        // pointwise conv, t-pair packed: acc[o][zz] holds (t0, t0+1)
        unsigned long long acc[4][2];
#pragma unroll
        for (int o = 0; o < 4; o++) {
            float b = sB[ob + o];
            acc[o][0] = pk(b, b);
            acc[o][1] = pk(b, b);
        }
#pragma unroll
        for (int c = 0; c < 32; c++) {
            float4 w4 = *reinterpret_cast<const float4*>(&sW[c * 32 + ob]);
            unsigned long long x0 = *reinterpret_cast<const unsigned long long*>(
                &sX[c * 256 + z0 * 32 + 2 * tp]);
            unsigned long long x1 = *reinterpret_cast<const unsigned long long*>(
                &sX[c * 256 + (z0 + 1) * 32 + 2 * tp]);
            unsigned long long w0 = pk(w4.x, w4.x), w1 = pk(w4.y, w4.y);
            unsigned long long w2 = pk(w4.z, w4.z), w3 = pk(w4.w, w4.w);
            fx2(acc[0][0], w0, x0); fx2(acc[0][1], w0, x1);
            fx2(acc[1][0], w1, x0); fx2(acc[1][1], w1, x1);
            fx2(acc[2][0], w2, x0); fx2(acc[2][1], w2, x1);
            fx2(acc[3][0], w3, x0); fx2(acc[3][1], w3, x1);
        }
        // inverse-t: acc += a.x * ct2 + a.y * (-st2)
#pragma unroll
        for (int kt = 0; kt < 8; kt++) {
            unsigned long long c2v = sCt2[tp * 8 + kt];
            unsigned long long s2v = sSt2[tp * 8 + kt];
#pragma unroll
            for (int o = 0; o < 4; o++) {
#pragma unroll
                for (int zz = 0; zz < 2; zz++) {
                    float2 a = sA[((ob + o) * 8 + z0 + zz) * 8 + kt];
                    fx2(acc[o][zz], pk(a.x, a.x), c2v);
                    fx2(acc[o][zz], pk(a.y, a.y), s2v);
                }
            }
        }
        if (outcrop) {
            if (tp < 12) {  // t = 2tp, 2tp+1 < 24
#pragma unroll
                for (int o = 0; o < 4; o++) {
#pragma unroll
                    for (int zz = 0; zz < 2; zz++) {
                        float2 v = upk(acc[o][zz]);
                        int z = zb + z0 + zz;
                        unsigned oidx = (((unsigned)xx * 24u + y) * 24u + z) * 24u + 2 * tp;
                        __stcs(reinterpret_cast<float2*>(
                                   outcrop + (size_t)(ob + o) * 331776u + oidx), v);
                    }
                }
            }
        } else {
#pragma unroll
            for (int o = 0; o < 4; o++) {
#pragma unroll
                for (int zz = 0; zz < 2; zz++) {
                    float2 v = upk(acc[o][zz]);
                    if (apply_gelu) { v.x = gelu_exact(v.x); v.y = gelu_exact(v.y); }
                    size_t base = (size_t)(ob + o) * NSITE4 +
                                  (((size_t)xx * 32u + y) * 32u + zb + z0 + zz) * 32u + 2 * tp;
                    __stcs(reinterpret_cast<float2*>(outfull + base), v);
                }
            }
        }
    }
}

// ---------------------------------------------------------------------------
extern "C" void kernel_launch(void* const* d_in, const int* in_sizes, int n_in,
                              void* d_out, int out_size) {
    const float* x = (const float*)d_in[0];
    const float* lw1 = (const float*)d_in[1];
    const float* lb1 = (const float*)d_in[2];
    const float* lw2 = (const float*)d_in[3];
    const float* lb2 = (const float*)d_in[4];
    const float* cw = (const float*)d_in[5];
    const float* cb = (const float*)d_in[6];
    const float* sw = (const float*)d_in[7];

    void *c2p, *c3p, *c4p, *c5p;
    cudaGetSymbolAddress(&c2p, g_c2);
    cudaGetSymbolAddress(&c3p, g_c3);
    cudaGetSymbolAddress(&c4p, g_c4);
    cudaGetSymbolAddress(&c5p, g_c5);
    float2* c2 = (float2*)c2p;
    float2* c3 = (float2*)c3p;
    float2* c4 = (float2*)c4p;
    float2* c5 = (float2*)c5p;

    const int SM_TZ = 61440;
    const int SM_FUSE = 92288;
    cudaFuncSetAttribute(fwd_tz2, cudaFuncAttributeMaxDynamicSharedMemorySize, SM_TZ);
    cudaFuncSetAttribute(fuse_inv_kernel, cudaFuncAttributeMaxDynamicSharedMemorySize, SM_FUSE);

    init_tables<<<1, 256>>>();
    lift_kernel<<<4096, 256>>>(x, lw1, lb1, lw2, lb2);

    for (int k = 0; k < 4; k++) {
        int flip = k & 1;
        fwd_tz2<<<4096, 256, SM_TZ>>>(flip);
        contract2<16, 32, true><<<1024, 256>>>(c2, c3, 128, 1);    // y: 32 -> 16
        contract2<16, 32, true><<<512, 256>>>(c3, c4, 2048, 16);   // x: 32 -> 16
        mix2<<<512, 256>>>(sw + (size_t)k * 67108864u);
        contract2<32, 16, false><<<1024, 256>>>(c5, c3, 2048, 32); // x: 16 -> 32
        contract2<32, 16, false><<<2048, 256>>>(c3, c2, 128, 2);   // y: 16 -> 32
        fuse_inv_kernel<<<1024, 512, SM_FUSE>>>(flip, cw + k * 1024, cb + k * 32,
                                                (k == 3) ? (float*)d_out : nullptr,
                                                (k < 3) ? 1 : 0);
    }
}

// round 15
// speedup vs baseline: 1.6257x; 1.0135x over previous
#include <cuda_runtime.h>
#include <math.h>

// ---------------------------------------------------------------------------
// TFNO4D encoder. Domain after padding: 32^4, channels 32.
// Spectral conv keeps Klist = {0..7, 24..31} in x,y,z; kt = 0..7 in t.
// Per layer: fwd_tz2 -> contract2(y) -> contract2(x) -> mix2 -> contract2(x^-1)
// -> contract2(y^-1) -> fuse_inv (inv-z + inv-t + pointwise + GELU/crop).
// R14 base + FFMA2 contract2 (R6 variant, measured faster) + mix2 unroll 8.
// ---------------------------------------------------------------------------

#define NSITE3 32768u
#define NSITE4 1048576u

__device__ float  g_bufA[32u * NSITE4];
__device__ float  g_bufB[32u * NSITE4];
__device__ float2 g_c2[32u * 32u * 32u * 16u * 8u];   // [C][X][Y][kz16][kt8]
__device__ float2 g_c3[32u * 32u * 16u * 16u * 8u];   // y-contracted
__device__ float2 g_c4[32u * 16u * 16u * 16u * 8u];   // [C][kx][ky][kz][kt]
__device__ float2 g_c5[32u * 16u * 16u * 16u * 8u];   // mixed

// Tables
__device__ float2 g_WtT[32 * 8];        // [t][kt]  exp(-2pi i kt t/32)
__device__ float4 g_WfP[32 * 16];       // [z][kzb*2+h] expanded fwd (fwd_tz2)
__device__ ulonglong2 g_WfE[16 * 32];   // [a][n] expanded fwd: {(c,c),(s,-s)}
__device__ ulonglong2 g_WiE[32 * 16];   // [n][a] expanded inv: {(c,c),(-s,s)}
__device__ float2 g_Wi[32 * 16];        // [n][a] inv spatial (plain, fuse_inv)
__device__ float  g_ct[32 * 8];         // f_k cos(2pi k t/32), f_0=1 else 2
__device__ float  g_st[32 * 8];         // f_k sin(2pi k t/32)

// Branch-free GELU: erf via Abramowitz-Stegun 7.1.26 (abs err <= 1.5e-7).
__device__ __forceinline__ float gelu_exact(float v) {
    float u = fabsf(v) * 0.70710678118654752f;
    float t = __fdividef(1.0f, fmaf(0.3275911f, u, 1.0f));
    float poly = t * fmaf(t, fmaf(t, fmaf(t, fmaf(t, 1.061405429f, -1.453152027f),
                                          1.421413741f), -0.284496736f), 0.254829592f);
    float e = __expf(-u * u);
    float erf_abs = fmaf(-poly, e, 1.0f);
    float erfv = copysignf(erf_abs, v);
    return 0.5f * v * (1.0f + erfv);
}

__device__ __forceinline__ unsigned long long pk(float a, float b) {
    unsigned long long r;
    asm("mov.b64 %0,{%1,%2};" : "=l"(r) : "f"(a), "f"(b));
    return r;
}
__device__ __forceinline__ float2 upk(unsigned long long u) {
    float2 v;
    asm("mov.b64 {%0,%1},%2;" : "=f"(v.x), "=f"(v.y) : "l"(u));
    return v;
}
__device__ __forceinline__ void fx2(unsigned long long& d, unsigned long long a,
                                    unsigned long long b) {
    asm("fma.rn.f32x2 %0,%1,%2,%0;" : "+l"(d) : "l"(a), "l"(b));
}

// ---------------------------------------------------------------------------
__global__ void init_tables() {
    int tid = threadIdx.x;
    const float STEP = 6.283185307179586f / 32.0f;
    for (int idx = tid; idx < 32 * 8; idx += blockDim.x) {
        int t = idx >> 3, kt = idx & 7;
        float ang = STEP * (float)((kt * t) & 31);
        g_WtT[idx] = make_float2(cosf(ang), -sinf(ang));
        float f = (kt == 0) ? 1.0f : 2.0f;
        g_ct[idx] = f * cosf(ang);
        g_st[idx] = f * sinf(ang);
    }
    for (int idx = tid; idx < 32 * 16; idx += blockDim.x) {
        int z = idx >> 4, r = idx & 15;
        int kzb = r >> 1, h = r & 1;
        int k = h ? (kzb + 24) : kzb;
        float ang = STEP * (float)((k * z) & 31);
        float2 w = make_float2(cosf(ang), -sinf(ang));
        g_WfP[idx] = make_float4(w.x, w.x, -w.y, w.y);
    }
    for (int idx = tid; idx < 16 * 32; idx += blockDim.x) {
        int a = idx >> 5, n = idx & 31;
        int k = (a < 8) ? a : (a + 16);
        float ang = STEP * (float)((k * n) & 31);
        float c = cosf(ang), s = sinf(ang);
        ulonglong2 e;
        e.x = pk(c, c);
        e.y = pk(s, -s);   // fwd w=(c,-s): acc += (c,c)*(vx,vy) + (s,-s)*(vy,vx)
        g_WfE[idx] = e;
    }
    for (int idx = tid; idx < 32 * 16; idx += blockDim.x) {
        int n = idx >> 4, a = idx & 15;
        int k = (a < 8) ? a : (a + 16);
        float ang = STEP * (float)((k * n) & 31);
        float c = cosf(ang), s = sinf(ang);
        ulonglong2 e;
        e.x = pk(c, c);
        e.y = pk(-s, s);   // inv w=(c,s)
        g_WiE[idx] = e;
        g_Wi[idx] = make_float2(c, s);
    }
}

// ---------------------------------------------------------------------------
// Lift: coords + input -> FC(7->16) -> GELU -> FC(16->32), zero outside 24^4.
__global__ void lift_kernel(const float* __restrict__ x,
                            const float* __restrict__ lw1, const float* __restrict__ lb1,
                            const float* __restrict__ lw2, const float* __restrict__ lb2) {
    __shared__ float w1[16 * 7], b1[16], w2[32 * 16], b2[32];
    int tid = threadIdx.x;
    for (int i = tid; i < 112; i += 256) w1[i] = lw1[i];
    for (int i = tid; i < 16; i += 256) b1[i] = lb1[i];
    for (int i = tid; i < 512; i += 256) w2[i] = lw2[i];
    for (int i = tid; i < 32; i += 256) b2[i] = lb2[i];
    __syncthreads();
    unsigned s = blockIdx.x * 256u + (unsigned)tid;
    int t = s & 31, z = (s >> 5) & 31, y = (s >> 10) & 31, xx = s >> 15;
    if (xx < 24 && y < 24 && z < 24 && t < 24) {
        unsigned ii = (((unsigned)xx * 24u + y) * 24u + z) * 24u + t;
        float v[7];
        v[0] = x[ii];
        v[1] = x[331776u + ii];
        v[2] = x[663552u + ii];
        v[3] = xx * (1.0f / 23.0f);
        v[4] = y * (1.0f / 23.0f);
        v[5] = z * (1.0f / 23.0f);
        v[6] = t * (1.0f / 23.0f);
        float h[16];
#pragma unroll
        for (int j = 0; j < 16; j++) {
            float a = b1[j];
#pragma unroll
            for (int c = 0; c < 7; c++) a += w1[j * 7 + c] * v[c];
            h[j] = gelu_exact(a);
        }
#pragma unroll
        for (int o = 0; o < 32; o++) {
            float a = b2[o];
#pragma unroll
            for (int j = 0; j < 16; j++) a += w2[o * 16 + j] * h[j];
            g_bufA[(size_t)o * NSITE4 + s] = a;
        }
    } else {
#pragma unroll
        for (int o = 0; o < 32; o++) g_bufA[(size_t)o * NSITE4 + s] = 0.0f;
    }
}

// ---------------------------------------------------------------------------
// Forward t-DFT (32 real -> 8 complex) + z-DFT (32 -> 16 modes).
// Warp per pencil (c,x,y); 8 pencils per 256-thread block.
__global__ void fwd_tz2(int flip) {
    const float* __restrict__ in = flip ? g_bufB : g_bufA;
    extern __shared__ char smraw[];
    float2* sS = (float2*)smraw;                  // 8 * 544 (row stride 17)
    float2* sCt = sS + 8 * 544;                   // 8 * 256
    float2* sWt = sCt + 2048;                     // 256
    ulonglong2* sWp = (ulonglong2*)(sWt + 256);   // 512
    int tid = threadIdx.x, lane = tid & 31, p = tid >> 5;
    for (int i = tid; i < 256; i += 256) sWt[i] = g_WtT[i];
    {
        const ulonglong2* src = (const ulonglong2*)g_WfP;
        for (int i = tid; i < 512; i += 256) sWp[i] = src[i];
    }
    int c = blockIdx.x >> 7, xx = (blockIdx.x >> 2) & 31, yg = blockIdx.x & 3;
    int y = yg * 8 + p;
    const float4* gp = (const float4*)(in + (size_t)c * NSITE4 + (((size_t)xx * 32u + y) * 32u) * 32u);
#pragma unroll
    for (int q = 0; q < 8; q++) {
        int idx4 = lane + 32 * q;
        float4 v = __ldcs(gp + idx4);
        int idx = idx4 * 2;
        sS[p * 544 + (idx >> 4) * 17 + (idx & 15)] = make_float2(v.x, v.y);
        sS[p * 544 + ((idx + 1) >> 4) * 17 + ((idx + 1) & 15)] = make_float2(v.z, v.w);
    }
    __syncthreads();
    {
        unsigned long long acc[8];
#pragma unroll
        for (int k = 0; k < 8; k++) acc[k] = 0ull;
        const float2* row = sS + p * 544 + lane * 17;
        const ulonglong2* wt2 = (const ulonglong2*)sWt;
#pragma unroll
        for (int tp = 0; tp < 16; tp++) {
            float2 v2 = row[tp];
            unsigned long long v0 = pk(v2.x, v2.x);
            unsigned long long v1 = pk(v2.y, v2.y);
            int t0 = 2 * tp;
#pragma unroll
            for (int kp = 0; kp < 4; kp++) {
                ulonglong2 wa = wt2[t0 * 4 + kp];
                fx2(acc[2 * kp], v0, wa.x);
                fx2(acc[2 * kp + 1], v0, wa.y);
                ulonglong2 wb = wt2[(t0 + 1) * 4 + kp];
                fx2(acc[2 * kp], v1, wb.x);
                fx2(acc[2 * kp + 1], v1, wb.y);
            }
        }
        float2* ct = sCt + p * 256 + lane * 8;
#pragma unroll
        for (int k = 0; k < 8; k++) ct[k] = upk(acc[k]);
    }
    __syncthreads();
    {
        int kzb = lane >> 2, ktq = lane & 3;
        unsigned long long a0 = 0, a1 = 0, a2 = 0, a3 = 0;
        const float2* ctp = sCt + p * 256;
#pragma unroll
        for (int z = 0; z < 32; z++) {
            float2 v0 = ctp[z * 8 + 2 * ktq];
            float2 v1 = ctp[z * 8 + 2 * ktq + 1];
            unsigned long long v0p = pk(v0.x, v0.y), v0s = pk(v0.y, v0.x);
            unsigned long long v1p = pk(v1.x, v1.y), v1s = pk(v1.y, v1.x);
            ulonglong2 wA = sWp[z * 16 + kzb * 2];
            ulonglong2 wB = sWp[z * 16 + kzb * 2 + 1];
            fx2(a0, wA.x, v0p); fx2(a0, wA.y, v0s);
            fx2(a1, wA.x, v1p); fx2(a1, wA.y, v1s);
            fx2(a2, wB.x, v0p); fx2(a2, wB.y, v0s);
            fx2(a3, wB.x, v1p); fx2(a3, wB.y, v1s);
        }
        float2* ob = g_c2 + (((size_t)c * 32u + xx) * 32u + y) * 128u;
        float2 r0 = upk(a0), r1 = upk(a1), r2 = upk(a2), r3 = upk(a3);
        *(float4*)(ob + kzb * 8 + 2 * ktq) = make_float4(r0.x, r0.y, r1.x, r1.y);
        *(float4*)(ob + (kzb + 8) * 8 + 2 * ktq) = make_float4(r2.x, r2.y, r3.x, r3.y);
    }
}

// ---------------------------------------------------------------------------
// Tiled complex contraction with packed FFMA2 (R6 variant, measured faster):
// out[k,i] = sum_n W[k,n] in[n,i]. 256 threads; 4 k x 2 i register tile.
template <int M, int L, bool FWD>
__global__ void contract2(const float2* __restrict__ in, float2* __restrict__ out,
                          int inner, int tiles) {
    constexpr int ITILE = 2048 / M;
    constexpr int IG = ITILE / 2;
    __shared__ ulonglong2 sW[M * L];
    __shared__ float2 sIn[L * ITILE];
    int outer = blockIdx.x / tiles;
    int tile = blockIdx.x - outer * tiles;
    int base = tile * ITILE;
    int tid = threadIdx.x;
    const ulonglong2* Wt = FWD ? g_WfE : g_WiE;
    for (int i = tid; i < M * L; i += 256) sW[i] = Wt[i];
    {
        const float4* ip4 = reinterpret_cast<const float4*>(in + (size_t)outer * L * inner + base);
        float4* s4 = reinterpret_cast<float4*>(sIn);
        constexpr int R4 = ITILE / 2;
        for (int idx = tid; idx < L * R4; idx += 256) {
            int n = idx / R4, r = idx - n * R4;
            s4[n * R4 + r] = ip4[(size_t)n * (inner >> 1) + r];
        }
    }
    __syncthreads();
    int ig = tid & (IG - 1);
    int kg = tid / IG;
    unsigned long long acc[4][2];
#pragma unroll
    for (int kk = 0; kk < 4; kk++) { acc[kk][0] = 0ull; acc[kk][1] = 0ull; }
    const float4* s4 = reinterpret_cast<const float4*>(sIn);
#pragma unroll
    for (int n = 0; n < L; n++) {
        float4 v = s4[n * (ITILE / 2) + ig];
        unsigned long long vp0 = pk(v.x, v.y), vs0 = pk(v.y, v.x);
        unsigned long long vp1 = pk(v.z, v.w), vs1 = pk(v.w, v.z);
#pragma unroll
        for (int kk = 0; kk < 4; kk++) {
            ulonglong2 w = sW[(kg * 4 + kk) * L + n];
            fx2(acc[kk][0], w.x, vp0);
            fx2(acc[kk][0], w.y, vs0);
            fx2(acc[kk][1], w.x, vp1);
            fx2(acc[kk][1], w.y, vs1);
        }
    }
#pragma unroll
    for (int kk = 0; kk < 4; kk++) {
        int k = kg * 4 + kk;
        float2 r0 = upk(acc[kk][0]), r1 = upk(acc[kk][1]);
        float4* op4 = reinterpret_cast<float4*>(out + ((size_t)outer * M + k) * inner + base);
        op4[ig] = make_float4(r0.x, r0.y, r1.x, r1.y);
    }
}

// ---------------------------------------------------------------------------
// Mode mixing: per corner (8) and (m1,m2), 64 contiguous (m3,m4) modes.
// unroll 8 on the c-loop for deeper outstanding-LDG pipeline.
__global__ void mix2(const float* __restrict__ wbase) {
    __shared__ float2 sIn[32 * 64];
    int bidx = blockIdx.x;
    int m2 = bidx & 7, m1 = (bidx >> 3) & 7, corner = bidx >> 6;
    int cz = corner & 1, cy = (corner >> 1) & 1, cx = corner >> 2;
    int kx = cx * 8 + m1, ky = cy * 8 + m2;
    int tid = threadIdx.x;  // 256
    unsigned base = (((unsigned)kx * 16u + ky) * 16u + (unsigned)cz * 8u) * 8u;
    {
        const float4* src4 = (const float4*)g_c4;
        float4* sIn4 = (float4*)sIn;
#pragma unroll
        for (int q = 0; q < 4; q++) {
            int idx = tid + 256 * q;
            int cc = idx >> 5, f = idx & 31;
            sIn4[cc * 32 + f] = src4[(size_t)cc * 16384u + (base >> 1) + f];
        }
    }
    __syncthreads();
    int og = tid >> 5, mp = tid & 31;
    float acc[4][4];
#pragma unroll
    for (int o = 0; o < 4; o++)
#pragma unroll
        for (int j = 0; j < 4; j++) acc[o][j] = 0.f;
    const float* wp0 = wbase + (size_t)corner * 8388608u + (size_t)(og * 4) * 8192u +
                       (size_t)(m1 * 8 + m2) * 128u + mp * 4;
    const float4* sIn4 = (const float4*)sIn;
#pragma unroll 8
    for (int c = 0; c < 32; c++) {
        float4 v = sIn4[c * 32 + mp];
        const float* wc = wp0 + (size_t)c * 262144u;
#pragma unroll
        for (int o = 0; o < 4; o++) {
            float4 w = __ldcs((const float4*)(wc + (size_t)o * 8192u));
            acc[o][0] += w.x * v.x - w.y * v.y;
            acc[o][1] += w.x * v.y + w.y * v.x;
            acc[o][2] += w.z * v.z - w.w * v.w;
            acc[o][3] += w.z * v.w + w.w * v.z;
        }
    }
    const float scale = 1.0f / 1048576.0f;
    float4* dst = (float4*)g_c5;
#pragma unroll
    for (int o = 0; o < 4; o++) {
        dst[(size_t)(og * 4 + o) * 16384u + (base >> 1) + mp] =
            make_float4(acc[o][0] * scale, acc[o][1] * scale,
                        acc[o][2] * scale, acc[o][3] * scale);
    }
}

// ---------------------------------------------------------------------------
// Fused inverse-z DFT + inverse-t real DFT + pointwise conv + bias
// (+GELU or crop). One block per (x,y), 512 threads.
// Thread = (tp16, zq4, og8): owns 4 o x 2 z x 2 t (t-pair packed FFMA2).
__global__ void fuse_inv_kernel(int flip, const float* __restrict__ cw,
                                const float* __restrict__ cb,
                                float* __restrict__ outcrop, int apply_gelu) {
    extern __shared__ char smemraw[];
    float2* sC = reinterpret_cast<float2*>(smemraw);            // 4096 [o][kz][kt]
    float2* sA = sC + 4096;                                     // 2048 [o][z8][kt]
    float2* sWi = sA + 2048;                                    // 512
    float*  sX = reinterpret_cast<float*>(sWi + 512);           // 8192 [c][z8][t]
    float*  sW = sX + 8192;                                     // 1024 [c][o] transposed
    float*  sB = sW + 1024;                                     // 32
    unsigned long long* sCt2 = reinterpret_cast<unsigned long long*>(sB + 32);  // 128 [tp][kt]
    unsigned long long* sSt2 = sCt2 + 128;                      // 128 (negated sin)

    int bx = blockIdx.x;
    int xx = bx >> 5, y = bx & 31;
    if (outcrop && (xx >= 24 || y >= 24)) return;
    const float* __restrict__ xin = flip ? g_bufB : g_bufA;
    float* __restrict__ outfull = flip ? g_bufA : g_bufB;
    int tid = threadIdx.x;  // 512

    {
        const float4* src = reinterpret_cast<const float4*>(g_c2);
        float4* dst = reinterpret_cast<float4*>(sC);
#pragma unroll
        for (int q = 0; q < 4; q++) {
            int idx4 = tid + 512 * q;
            int o = idx4 >> 6, r = idx4 & 63;
            dst[idx4] = src[(((size_t)o * 32u + xx) * 32u + y) * 64u + r];
        }
    }
    sWi[tid] = g_Wi[tid];
    // transpose conv weights into [c][o]
    sW[tid] = cw[(tid & 31) * 32 + (tid >> 5)];
    {
        int i1 = tid + 512;
        sW[i1] = cw[(i1 & 31) * 32 + (i1 >> 5)];
    }
    if (tid < 32) sB[tid] = cb[tid];
    if (tid < 128) {
        int tpp = tid >> 3, kt = tid & 7;
        sCt2[tid] = pk(g_ct[(2 * tpp) * 8 + kt], g_ct[(2 * tpp + 1) * 8 + kt]);
        sSt2[tid] = pk(-g_st[(2 * tpp) * 8 + kt], -g_st[(2 * tpp + 1) * 8 + kt]);
    }

    int tp = tid & 15, zq = (tid >> 4) & 3, og = tid >> 6;  // og 0..7
    int ob = og * 4, z0 = zq * 2;

    for (int zb = 0; zb < 32; zb += 8) {
        if (outcrop && zb >= 24) break;
        // prefetch x chunk into registers
        float4 xr[4];
#pragma unroll
        for (int q = 0; q < 4; q++) {
            int idx4 = tid + 512 * q;
            int c = idx4 >> 6, r = idx4 & 63;
            xr[q] = __ldcs(reinterpret_cast<const float4*>(
                xin + (size_t)c * NSITE4 + (((size_t)xx * 32u + y) * 32u + zb) * 32u) + r);
        }
        __syncthreads();
        // inverse-z: a[o][z][kt] = sum_kz Wi[zb+z][kz] * sC[o][kz][kt]
#pragma unroll
        for (int j = 0; j < 4; j++) {
            int idx = tid + 512 * j;
            int o = idx >> 6, rem = idx & 63;
            int z = rem >> 3, kt = rem & 7;
            float2 a = make_float2(0.f, 0.f);
#pragma unroll
            for (int kz = 0; kz < 16; kz++) {
                float2 w = sWi[(zb + z) * 16 + kz];
                float2 v = sC[(o * 16 + kz) * 8 + kt];
                a.x += w.x * v.x - w.y * v.y;
                a.y += w.x * v.y + w.y * v.x;
            }
            sA[(o * 8 + z) * 8 + kt] = a;
        }
        {
            float4* dst = reinterpret_cast<float4*>(sX);
#pragma unroll
            for (int q = 0; q < 4; q++) dst[tid + 512 * q] = xr[q];
        }
        __syncthreads();
        // pointwise conv, t-pair packed: acc[o][zz] holds (t0, t0+1)
        unsigned long long acc[4][2];
#pragma unroll
        for (int o = 0; o < 4; o++) {
            float b = sB[ob + o];
            acc[o][0] = pk(b, b);
            acc[o][1] = pk(b, b);
        }
#pragma unroll
        for (int c = 0; c < 32; c++) {
            float4 w4 = *reinterpret_cast<const float4*>(&sW[c * 32 + ob]);
            unsigned long long x0 = *reinterpret_cast<const unsigned long long*>(
                &sX[c * 256 + z0 * 32 + 2 * tp]);
            unsigned long long x1 = *reinterpret_cast<const unsigned long long*>(
                &sX[c * 256 + (z0 + 1) * 32 + 2 * tp]);
            unsigned long long w0 = pk(w4.x, w4.x), w1 = pk(w4.y, w4.y);
            unsigned long long w2 = pk(w4.z, w4.z), w3 = pk(w4.w, w4.w);
            fx2(acc[0][0], w0, x0); fx2(acc[0][1], w0, x1);
            fx2(acc[1][0], w1, x0); fx2(acc[1][1], w1, x1);
            fx2(acc[2][0], w2, x0); fx2(acc[2][1], w2, x1);
            fx2(acc[3][0], w3, x0); fx2(acc[3][1], w3, x1);
        }
        // inverse-t: acc += a.x * ct2 + a.y * (-st2)
#pragma unroll
        for (int kt = 0; kt < 8; kt++) {
            unsigned long long c2v = sCt2[tp * 8 + kt];
            unsigned long long s2v = sSt2[tp * 8 + kt];
#pragma unroll
            for (int o = 0; o < 4; o++) {
#pragma unroll
                for (int zz = 0; zz < 2; zz++) {
                    float2 a = sA[((ob + o) * 8 + z0 + zz) * 8 + kt];
                    fx2(acc[o][zz], pk(a.x, a.x), c2v);
                    fx2(acc[o][zz], pk(a.y, a.y), s2v);
                }
            }
        }
        if (outcrop) {
            if (tp < 12) {  // t = 2tp, 2tp+1 < 24
#pragma unroll
                for (int o = 0; o < 4; o++) {
#pragma unroll
                    for (int zz = 0; zz < 2; zz++) {
                        float2 v = upk(acc[o][zz]);
                        int z = zb + z0 + zz;
                        unsigned oidx = (((unsigned)xx * 24u + y) * 24u + z) * 24u + 2 * tp;
                        __stcs(reinterpret_cast<float2*>(
                                   outcrop + (size_t)(ob + o) * 331776u + oidx), v);
                    }
                }
            }
        } else {
#pragma unroll
            for (int o = 0; o < 4; o++) {
#pragma unroll
                for (int zz = 0; zz < 2; zz++) {
                    float2 v = upk(acc[o][zz]);
                    if (apply_gelu) { v.x = gelu_exact(v.x); v.y = gelu_exact(v.y); }
                    size_t base = (size_t)(ob + o) * NSITE4 +
                                  (((size_t)xx * 32u + y) * 32u + zb + z0 + zz) * 32u + 2 * tp;
                    __stcs(reinterpret_cast<float2*>(outfull + base), v);
                }
            }
        }
    }
}

// ---------------------------------------------------------------------------
extern "C" void kernel_launch(void* const* d_in, const int* in_sizes, int n_in,
                              void* d_out, int out_size) {
    const float* x = (const float*)d_in[0];
    const float* lw1 = (const float*)d_in[1];
    const float* lb1 = (const float*)d_in[2];
    const float* lw2 = (const float*)d_in[3];
    const float* lb2 = (const float*)d_in[4];
    const float* cw = (const float*)d_in[5];
    const float* cb = (const float*)d_in[6];
    const float* sw = (const float*)d_in[7];

    void *c2p, *c3p, *c4p, *c5p;
    cudaGetSymbolAddress(&c2p, g_c2);
    cudaGetSymbolAddress(&c3p, g_c3);
    cudaGetSymbolAddress(&c4p, g_c4);
    cudaGetSymbolAddress(&c5p, g_c5);
    float2* c2 = (float2*)c2p;
    float2* c3 = (float2*)c3p;
    float2* c4 = (float2*)c4p;
    float2* c5 = (float2*)c5p;

    const int SM_TZ = 61440;
    const int SM_FUSE = 92288;
    cudaFuncSetAttribute(fwd_tz2, cudaFuncAttributeMaxDynamicSharedMemorySize, SM_TZ);
    cudaFuncSetAttribute(fuse_inv_kernel, cudaFuncAttributeMaxDynamicSharedMemorySize, SM_FUSE);

    init_tables<<<1, 256>>>();
    lift_kernel<<<4096, 256>>>(x, lw1, lb1, lw2, lb2);

    for (int k = 0; k < 4; k++) {
        int flip = k & 1;
        fwd_tz2<<<4096, 256, SM_TZ>>>(flip);
        contract2<16, 32, true><<<1024, 256>>>(c2, c3, 128, 1);    // y: 32 -> 16
        contract2<16, 32, true><<<512, 256>>>(c3, c4, 2048, 16);   // x: 32 -> 16
        mix2<<<512, 256>>>(sw + (size_t)k * 67108864u);
        contract2<32, 16, false><<<1024, 256>>>(c5, c3, 2048, 32); // x: 16 -> 32
        contract2<32, 16, false><<<2048, 256>>>(c3, c2, 128, 2);   // y: 16 -> 32
        fuse_inv_kernel<<<1024, 512, SM_FUSE>>>(flip, cw + k * 1024, cb + k * 32,
                                                (k == 3) ? (float*)d_out : nullptr,
                                                (k < 3) ? 1 : 0);
    }
}